// round 10
// baseline (speedup 1.0000x reference)
#include <cuda_runtime.h>
#include <cuda_fp16.h>
#include <math.h>

#define B_    64
#define S_    1024
#define D_    800
#define MS_   16
#define T_    32
#define H_    200
#define NS_   12
#define NSPAN (B_*MS_)        // 1024
#define MROWS (NSPAN*T_)      // 32768
#define KDIM  D_              // 800
#define KP    832             // GEMM K padded (52 k-slices of 16)
#define KP2   (KP/2)          // 416 u32 per row
#define NSLICE (KP/16)        // 52
#define G4H   (4*H_)          // 800
#define NCOLS 1600
#define NCPAD 1664
#define PSPAN 8
#define KC    64
#define KC2   (KC/2)
#define PITCH 40              // GEMM smem pitch (u32): LDS.64 conflict-free

typedef unsigned long long ull;

// -------- scratch (static device arrays; no runtime alloc) ------------------
__device__ __half   g_Zh[2][(size_t)MROWS * G4H];  // fp16 Z, [row][u*4+gate]
__device__ unsigned g_A16[(size_t)MROWS * KP2];    // gathered A fp16, slice-interleaved
__device__ unsigned g_B16[(size_t)NCPAD * KP2];    // Wih^T n-major fp16, slice-interleaved
__device__ float4   g_Wp[2][H_ * H_];              // recurrent weights [dir][k*H+u]
__device__ float    g_biasC[NCPAD];
__device__ float    g_feats[(size_t)NSPAN * 2 * H_];
__device__ int      g_rows[MROWS];
__device__ int      g_order[NSPAN];
__device__ int      g_cnt;

__device__ __forceinline__ unsigned pack_h2(float x0, float x1) {
    __half2 h = __floats2half2_rn(x0, x1);
    return *reinterpret_cast<unsigned*>(&h);
}

// slice interleave: slot 2t = kpair t, slot 2t+1 = kpair t+4  (t = 0..3)

// ---------------------------------------------------------------------------
// Fused pack + prep. Block 0 (1024 threads) additionally runs the prefix-scan
// (compacted rows) and descending counting-sort of spans. All blocks pack
// Wih^T -> fp16 slice-interleaved, gate-pack Whh, combine biases.
// ---------------------------------------------------------------------------
__global__ __launch_bounds__(1024) void packprep_kernel(
        const float* __restrict__ Wih_f, const float* __restrict__ Whh_f,
        const float* __restrict__ bih_f, const float* __restrict__ bhh_f,
        const float* __restrict__ Wih_b, const float* __restrict__ Whh_b,
        const float* __restrict__ bih_b, const float* __restrict__ bhh_b,
        const int*   __restrict__ lens) {
    // ---- prep (block 0 only) ----
    if (blockIdx.x == 0) {
        __shared__ int s[NSPAN];
        __shared__ int wcnt[32][T_ + 1];
        __shared__ int st[T_ + 1];
        __shared__ int tot[T_ + 1];
        int tid = threadIdx.x;
        int lane = tid & 31, w = tid >> 5;
        int l = min(max(lens[tid], 0), T_);
        s[tid] = l;
        for (int b = lane; b <= T_; b += 32) wcnt[w][b] = 0;
        __syncthreads();
        for (int d = 1; d < NSPAN; d <<= 1) {
            int v = (tid >= d) ? s[tid - d] : 0;
            __syncthreads();
            s[tid] += v;
            __syncthreads();
        }
        int off = s[tid] - l;
        for (int t = 0; t < l; t++) g_rows[off + t] = tid * T_ + t;
        if (tid == NSPAN - 1) g_cnt = s[tid];

        unsigned mask = __match_any_sync(0xffffffffu, l);
        int rin = __popc(mask & ((1u << lane) - 1u));
        if (rin == 0) wcnt[w][l] = __popc(mask);
        __syncthreads();
        if (tid <= T_) {
            int acc = 0;
            for (int ww = 0; ww < 32; ww++) {
                int c = wcnt[ww][tid];
                wcnt[ww][tid] = acc;
                acc += c;
            }
            tot[tid] = acc;
        }
        __syncthreads();
        if (tid == 0) {
            int a = 0;
            for (int b = T_; b >= 0; b--) { st[b] = a; a += tot[b]; }  // descending
        }
        __syncthreads();
        g_order[st[l] + wcnt[w][l] + rin] = tid;
    }

    // ---- pack (all blocks) ----
    int stride = gridDim.x * blockDim.x;
    int tid0   = blockIdx.x * blockDim.x + threadIdx.x;

    for (int idx = tid0; idx < NCPAD * NSLICE; idx += stride) {
        int j = idx / NSLICE, ks = idx % NSLICE;
        int k0 = ks * 16;
        float xs[16];
#pragma unroll
        for (int e = 0; e < 16; e++) {
            int k = k0 + e;
            float v = 0.f;
            if (j < NCOLS && k < KDIM)
                v = (j < G4H) ? Wih_f[(size_t)j * D_ + k]
                              : Wih_b[(size_t)(j - G4H) * D_ + k];
            xs[e] = v;
        }
        unsigned slots[8];
#pragma unroll
        for (int t = 0; t < 4; t++) {
            slots[2 * t]     = pack_h2(xs[2 * t],     xs[2 * t + 1]);
            slots[2 * t + 1] = pack_h2(xs[2 * t + 8], xs[2 * t + 9]);
        }
        unsigned* dst = &g_B16[(size_t)j * KP2 + ks * 8];
        *reinterpret_cast<uint4*>(dst)     = *reinterpret_cast<uint4*>(&slots[0]);
        *reinterpret_cast<uint4*>(dst + 4) = *reinterpret_cast<uint4*>(&slots[4]);
    }
    for (int idx = tid0; idx < 2 * H_ * H_; idx += stride) {
        int dir = idx / (H_ * H_);
        int rem = idx % (H_ * H_);
        int k = rem / H_, u = rem % H_;
        const float* Whh = dir ? Whh_b : Whh_f;
        float4 v;
        v.x = Whh[(size_t)(0 * H_ + u) * H_ + k];
        v.y = Whh[(size_t)(1 * H_ + u) * H_ + k];
        v.z = Whh[(size_t)(2 * H_ + u) * H_ + k];
        v.w = Whh[(size_t)(3 * H_ + u) * H_ + k];
        g_Wp[dir][k * H_ + u] = v;
    }
    for (int idx = tid0; idx < NCPAD; idx += stride) {
        float v = 0.f;
        if (idx < NCOLS) {
            int dir = idx / G4H, jj = idx % G4H;
            v = dir ? (bih_b[jj] + bhh_b[jj]) : (bih_f[jj] + bhh_f[jj]);
        }
        g_biasC[idx] = v;
    }
}

// ---------------------------------------------------------------------------
// Gather A -> fp16, slice-interleaved.
// ---------------------------------------------------------------------------
__global__ void gather_split(const float* __restrict__ hidden,
                             const int*   __restrict__ starts) {
    int idx = blockIdx.x * blockDim.x + threadIdx.x;
    int total = g_cnt * NSLICE;
    if (idx >= total) return;
    int m = idx / NSLICE, ks = idx % NSLICE;
    int k0 = ks * 16;
    float xs[16];
    if (k0 < KDIM) {
        int r = g_rows[m];
        int sp = r >> 5, t = r & 31;
        int b = sp >> 4, mm = sp & 15;
        int src = min(max(starts[b * MS_ + mm] + t, 0), S_ - 1);
        const float* base = &hidden[((size_t)b * S_ + src) * D_ + k0];
#pragma unroll
        for (int e = 0; e < 4; e++) {
            float4 v = *reinterpret_cast<const float4*>(base + 4 * e);
            xs[4 * e + 0] = v.x; xs[4 * e + 1] = v.y;
            xs[4 * e + 2] = v.z; xs[4 * e + 3] = v.w;
        }
    } else {
#pragma unroll
        for (int e = 0; e < 16; e++) xs[e] = 0.f;
    }
    unsigned slots[8];
#pragma unroll
    for (int t = 0; t < 4; t++) {
        slots[2 * t]     = pack_h2(xs[2 * t],     xs[2 * t + 1]);
        slots[2 * t + 1] = pack_h2(xs[2 * t + 8], xs[2 * t + 9]);
    }
    unsigned* dst = &g_A16[(size_t)m * KP2 + ks * 8];
    *reinterpret_cast<uint4*>(dst)     = *reinterpret_cast<uint4*>(&slots[0]);
    *reinterpret_cast<uint4*>(dst + 4) = *reinterpret_cast<uint4*>(&slots[4]);
}

// ---------------------------------------------------------------------------
// fp16 GEMM: 4 warps, 64x64 warp tile, cp.async double-buffered.
// Epilogue: bias + fp16 interleaved scatter-store [row][u][gate].
// ---------------------------------------------------------------------------
#define MMA_FP16(d, a, b)                                                       \
    asm volatile("mma.sync.aligned.m16n8k16.row.col.f32.f16.f16.f32 "           \
                 "{%0,%1,%2,%3}, {%4,%5,%6,%7}, {%8,%9}, {%0,%1,%2,%3};"        \
                 : "+f"(d[0]), "+f"(d[1]), "+f"(d[2]), "+f"(d[3])               \
                 : "r"(a[0]), "r"(a[1]), "r"(a[2]), "r"(a[3]),                  \
                   "r"(b[0]), "r"(b[1]));

__device__ __forceinline__ void cp16(unsigned* smem_ptr, const unsigned* gptr) {
    unsigned saddr = (unsigned)__cvta_generic_to_shared(smem_ptr);
    asm volatile("cp.async.cg.shared.global [%0], [%1], 16;" :: "r"(saddr), "l"(gptr));
}

#define MAT_TILE (128 * PITCH)          // 5120 u32
#define STG      (2 * MAT_TILE)         // 10240 u32/stage (40KB)

extern __shared__ unsigned smem_u[];

__global__ __launch_bounds__(128, 2) void gemm_tc(void) {
    const int cnt = g_cnt;
    const int m0  = blockIdx.y * 128;
    if (m0 >= cnt) return;
    const int n0  = blockIdx.x * 128;

    __shared__ int rowIdx[128];
    int tid = threadIdx.x;
    rowIdx[tid] = (m0 + tid < cnt) ? g_rows[m0 + tid] : -1;

    float acc[32][4];                     // mt(4) x nt(8)
#pragma unroll
    for (int i = 0; i < 32; i++)
#pragma unroll
        for (int q = 0; q < 4; q++) acc[i][q] = 0.f;

    int lane = tid & 31, wid = tid >> 5;  // 4 warps
    int wm = wid >> 1, wn = wid & 1;      // 2x2 warp grid
    int g = lane >> 2, tg = lane & 3;

    auto load_stage = [&](int stage, int k0u) {
        unsigned* As = smem_u + stage * STG;
        unsigned* Bs = As + MAT_TILE;
#pragma unroll
        for (int i = 0; i < 8; i++) {
            int id = tid + i * 128;
            int m = id >> 3, c = id & 7;
            cp16(&As[m * PITCH + c * 4], &g_A16[(size_t)(m0 + m) * KP2 + k0u + c * 4]);
        }
#pragma unroll
        for (int i = 0; i < 8; i++) {
            int id = tid + i * 128;
            int n = id >> 3, c = id & 7;
            cp16(&Bs[n * PITCH + c * 4], &g_B16[(size_t)(n0 + n) * KP2 + k0u + c * 4]);
        }
    };

    const int NITER = KP / KC;   // 13
    load_stage(0, 0);
    asm volatile("cp.async.commit_group;");

    for (int it = 0; it < NITER; it++) {
        if (it + 1 < NITER) load_stage((it + 1) & 1, (it + 1) * KC2);
        asm volatile("cp.async.commit_group;");
        asm volatile("cp.async.wait_group 1;");
        __syncthreads();

        const unsigned* As = smem_u + (it & 1) * STG;
        const unsigned* Bs = As + MAT_TILE;

#pragma unroll
        for (int ks = 0; ks < 4; ks++) {
            int kp = ks * 8;
            unsigned af[4][4];
#pragma unroll
            for (int mt = 0; mt < 4; mt++) {
                int r0 = wm * 64 + mt * 16 + g;
                ull v0 = *reinterpret_cast<const ull*>(As + r0 * PITCH + kp + 2 * tg);
                ull v1 = *reinterpret_cast<const ull*>(As + (r0 + 8) * PITCH + kp + 2 * tg);
                af[mt][0] = (unsigned)v0;
                af[mt][2] = (unsigned)(v0 >> 32);
                af[mt][1] = (unsigned)v1;
                af[mt][3] = (unsigned)(v1 >> 32);
            }
            unsigned bf[8][2];
#pragma unroll
            for (int nt = 0; nt < 8; nt++) {
                int c = wn * 64 + nt * 8 + g;
                ull v = *reinterpret_cast<const ull*>(Bs + c * PITCH + kp + 2 * tg);
                bf[nt][0] = (unsigned)v;
                bf[nt][1] = (unsigned)(v >> 32);
            }
#pragma unroll
            for (int mt = 0; mt < 4; mt++)
#pragma unroll
                for (int nt = 0; nt < 8; nt++)
                    MMA_FP16(acc[mt * 8 + nt], af[mt], bf[nt]);
        }
        __syncthreads();
    }

    // epilogue: bias + fp16 interleaved scatter-store
#pragma unroll
    for (int mt = 0; mt < 4; mt++) {
        int lr0 = wm * 64 + mt * 16 + g;
#pragma unroll
        for (int nt = 0; nt < 8; nt++) {
            int c = n0 + wn * 64 + nt * 8 + tg * 2;
            if (c >= NCOLS) continue;
            float* a = acc[mt * 8 + nt];
#pragma unroll
            for (int h = 0; h < 2; h++) {
                int lr = lr0 + h * 8;
                if (m0 + lr < cnt) {
                    int rid = rowIdx[lr];
#pragma unroll
                    for (int e = 0; e < 2; e++) {
                        int j = c + e;
                        float v = a[h * 2 + e] + g_biasC[j];
                        int dirb = (j >= G4H);
                        int cc   = j - dirb * G4H;
                        int gate = cc / H_, u = cc - gate * H_;
                        g_Zh[dirb][(size_t)rid * G4H + u * 4 + gate] = __float2half_rn(v);
                    }
                }
            }
        }
    }
}

// ---------------------------------------------------------------------------
// Recurrence: one 8-span group per CTA, grid (128, 2), descending-length
// order. Z read as one LDG.64 (4 gates) per span per step.
// ---------------------------------------------------------------------------
__device__ __forceinline__ float fast_sig(float x)  { return 1.f / (1.f + __expf(-x)); }
__device__ __forceinline__ float fast_tanh(float x) {
    float t = __expf(-2.f * x);
    return __fdividef(1.f - t, 1.f + t);
}

__global__ __launch_bounds__(224) void lstm_kernel(const int* __restrict__ span_lens) {
    __shared__ float4 h4[2][PSPAN][H_ / 4];
    __shared__ int    sp_sh[PSPAN];
    __shared__ int    len_sh[PSPAN];

    int tid = threadIdx.x;
    int dir = blockIdx.y;
    int u   = tid;
    bool act = u < H_;
    int n0  = blockIdx.x * PSPAN;

    const __half* Zh = g_Zh[dir];
    const float4* Wp = g_Wp[dir];

    if (tid < PSPAN) {
        int sp = g_order[n0 + tid];
        sp_sh[tid]  = sp;
        len_sh[tid] = min(max(span_lens[sp], 0), T_);
    }
    {
        float* hz = (float*)h4;
        for (int i = tid; i < PSPAN * H_; i += 224) hz[i] = 0.f;
    }
    __syncthreads();

    int maxL = 0;
#pragma unroll
    for (int p = 0; p < PSPAN; p++) maxL = max(maxL, len_sh[p]);

    float c[PSPAN], feat[PSPAN], hreg[PSPAN];
#pragma unroll
    for (int p = 0; p < PSPAN; p++) { c[p] = 0.f; feat[p] = 0.f; hreg[p] = 0.f; }

    int buf = 0;
    for (int s = 0; s < maxL; s++) {
        float a0[PSPAN], a1[PSPAN], a2[PSPAN], a3[PSPAN];
        if (act) {
#pragma unroll
            for (int p = 0; p < PSPAN; p++) {
                int L = len_sh[p];
                int t = dir ? (L - 1 - s) : s;
                if (s >= L) t = 0;
                uint2 zv = *reinterpret_cast<const uint2*>(
                    Zh + ((size_t)sp_sh[p] * T_ + t) * G4H + u * 4);
                float2 f01 = __half22float2(*reinterpret_cast<__half2*>(&zv.x));
                float2 f23 = __half22float2(*reinterpret_cast<__half2*>(&zv.y));
                a0[p] = f01.x;
                a1[p] = f01.y;
                a2[p] = f23.x;
                a3[p] = f23.y;
            }
#pragma unroll 2
            for (int k = 0; k < H_; k += 4) {
                float4 w0 = Wp[(k + 0) * H_ + u];
                float4 w1 = Wp[(k + 1) * H_ + u];
                float4 w2 = Wp[(k + 2) * H_ + u];
                float4 w3 = Wp[(k + 3) * H_ + u];
#pragma unroll
                for (int p = 0; p < PSPAN; p++) {
                    float4 hv = h4[buf][p][k >> 2];
                    a0[p] += w0.x * hv.x; a0[p] += w1.x * hv.y;
                    a0[p] += w2.x * hv.z; a0[p] += w3.x * hv.w;
                    a1[p] += w0.y * hv.x; a1[p] += w1.y * hv.y;
                    a1[p] += w2.y * hv.z; a1[p] += w3.y * hv.w;
                    a2[p] += w0.z * hv.x; a2[p] += w1.z * hv.y;
                    a2[p] += w2.z * hv.z; a2[p] += w3.z * hv.w;
                    a3[p] += w0.w * hv.x; a3[p] += w1.w * hv.y;
                    a3[p] += w2.w * hv.z; a3[p] += w3.w * hv.w;
                }
            }
#pragma unroll
            for (int p = 0; p < PSPAN; p++) {
                if (s < len_sh[p]) {
                    float ig = fast_sig(a0[p]);
                    float fg = fast_sig(a1[p]);
                    float gg = fast_tanh(a2[p]);
                    float og = fast_sig(a3[p]);
                    float cn = fg * c[p] + ig * gg;
                    c[p] = cn;
                    hreg[p] = og * fast_tanh(cn);
                    feat[p] += hreg[p];
                }
                ((float*)&h4[buf ^ 1][p][0])[u] = hreg[p];
            }
        }
        __syncthreads();
        buf ^= 1;
    }

    if (act) {
#pragma unroll
        for (int p = 0; p < PSPAN; p++)
            g_feats[(size_t)sp_sh[p] * (2 * H_) + dir * H_ + u] = feat[p];
    }
}

// ---------------------------------------------------------------------------
// logits
// ---------------------------------------------------------------------------
__global__ __launch_bounds__(192) void logits_kernel(const float* __restrict__ slot_embs,
                                                     const float* __restrict__ slot_mask,
                                                     float* __restrict__ out) {
    __shared__ float f_sm[16][2 * H_];
    __shared__ float se_sm[2 * H_ * NS_];

    int tid = threadIdx.x;
    int n0  = blockIdx.x * 16;

    for (int i = tid; i < 2 * H_ * NS_; i += blockDim.x) se_sm[i] = slot_embs[i];
    for (int i = tid; i < 16 * 2 * H_; i += blockDim.x) {
        int sp = i / (2 * H_), h = i % (2 * H_);
        f_sm[sp][h] = g_feats[(size_t)(n0 + sp) * (2 * H_) + h];
    }
    __syncthreads();

    int sp = tid / NS_, ns = tid % NS_;
    float acc = 0.f;
#pragma unroll 8
    for (int h = 0; h < 2 * H_; h++) acc += f_sm[sp][h] * se_sm[h * NS_ + ns];
    out[(n0 + sp) * NS_ + ns] = acc * slot_mask[n0 + sp];
}

// ---------------------------------------------------------------------------
extern "C" void kernel_launch(void* const* d_in, const int* in_sizes, int n_in,
                              void* d_out, int out_size) {
    const float* hidden    = (const float*)d_in[0];
    const float* Wih_f     = (const float*)d_in[1];
    const float* Whh_f     = (const float*)d_in[2];
    const float* bih_f     = (const float*)d_in[3];
    const float* bhh_f     = (const float*)d_in[4];
    const float* Wih_b     = (const float*)d_in[5];
    const float* Whh_b     = (const float*)d_in[6];
    const float* bih_b     = (const float*)d_in[7];
    const float* bhh_b     = (const float*)d_in[8];
    const float* slot_embs = (const float*)d_in[9];
    const int*   starts    = (const int*)d_in[10];
    const int*   lens      = (const int*)d_in[11];
    const float* slot_mask = (const float*)d_in[12];
    float* out = (float*)d_out;

    const int gemm_smem = 2 * STG * (int)sizeof(unsigned);   // 81920 B
    cudaFuncSetAttribute(gemm_tc, cudaFuncAttributeMaxDynamicSharedMemorySize, gemm_smem);

    // launch order: lstm is the 4th launch -> lands in ncu's profile window
    packprep_kernel<<<256, 1024>>>(Wih_f, Whh_f, bih_f, bhh_f,
                                   Wih_b, Whh_b, bih_b, bhh_b, lens);

    gather_split<<<(MROWS * NSLICE + 255) / 256, 256>>>(hidden, starts);

    dim3 ggrid(NCPAD / 128, MROWS / 128);
    gemm_tc<<<ggrid, 128, gemm_smem>>>();

    dim3 lgrid(128, 2);   // 256 CTAs, descending-length groups
    lstm_kernel<<<lgrid, 224>>>(lens);

    logits_kernel<<<NSPAN / 16, 192>>>(slot_embs, slot_mask, out);
}

// round 11
// speedup vs baseline: 1.0266x; 1.0266x over previous
#include <cuda_runtime.h>
#include <cuda_fp16.h>
#include <math.h>

#define B_    64
#define S_    1024
#define D_    800
#define MS_   16
#define T_    32
#define H_    200
#define NS_   12
#define NSPAN (B_*MS_)        // 1024
#define MROWS (NSPAN*T_)      // 32768
#define KDIM  D_              // 800
#define KP    832             // GEMM K padded (52 k-slices of 16)
#define KP2   (KP/2)          // 416 u32 per row
#define NSLICE (KP/16)        // 52
#define G4H   (4*H_)          // 800
#define NCOLS 1600
#define NCPAD 1664
#define PSPAN 8
#define KC    64
#define KC2   (KC/2)
#define PITCH 40              // GEMM smem pitch (u32): LDS.64 conflict-free

typedef unsigned long long ull;

// -------- scratch (static device arrays; no runtime alloc) ------------------
__device__ __half   g_Zh[2][(size_t)MROWS * G4H];  // fp16 Z, gate-major [row][gate*200+u]
__device__ unsigned g_A16[(size_t)MROWS * KP2];    // gathered A fp16, slice-interleaved
__device__ unsigned g_B16[(size_t)NCPAD * KP2];    // Wih^T n-major fp16, slice-interleaved
__device__ float4   g_Wp[2][H_ * H_];              // recurrent weights [dir][k*H+u]
__device__ float    g_biasC[NCPAD];
__device__ float    g_feats[(size_t)NSPAN * 2 * H_];
__device__ int      g_rows[MROWS];
__device__ int      g_order[NSPAN];
__device__ int      g_cnt;

__device__ __forceinline__ unsigned pack_h2(float x0, float x1) {
    __half2 h = __floats2half2_rn(x0, x1);
    return *reinterpret_cast<unsigned*>(&h);
}

// slice interleave: slot 2t = kpair t, slot 2t+1 = kpair t+4  (t = 0..3)

// ---------------------------------------------------------------------------
// Fused pack + prep. Block 0 runs the prefix-scan and descending counting
// sort; all blocks pack Wih^T -> fp16 slice-interleaved, Whh, biases.
// ---------------------------------------------------------------------------
__global__ __launch_bounds__(1024) void packprep_kernel(
        const float* __restrict__ Wih_f, const float* __restrict__ Whh_f,
        const float* __restrict__ bih_f, const float* __restrict__ bhh_f,
        const float* __restrict__ Wih_b, const float* __restrict__ Whh_b,
        const float* __restrict__ bih_b, const float* __restrict__ bhh_b,
        const int*   __restrict__ lens) {
    if (blockIdx.x == 0) {
        __shared__ int s[NSPAN];
        __shared__ int wcnt[32][T_ + 1];
        __shared__ int st[T_ + 1];
        __shared__ int tot[T_ + 1];
        int tid = threadIdx.x;
        int lane = tid & 31, w = tid >> 5;
        int l = min(max(lens[tid], 0), T_);
        s[tid] = l;
        for (int b = lane; b <= T_; b += 32) wcnt[w][b] = 0;
        __syncthreads();
        for (int d = 1; d < NSPAN; d <<= 1) {
            int v = (tid >= d) ? s[tid - d] : 0;
            __syncthreads();
            s[tid] += v;
            __syncthreads();
        }
        int off = s[tid] - l;
        for (int t = 0; t < l; t++) g_rows[off + t] = tid * T_ + t;
        if (tid == NSPAN - 1) g_cnt = s[tid];

        unsigned mask = __match_any_sync(0xffffffffu, l);
        int rin = __popc(mask & ((1u << lane) - 1u));
        if (rin == 0) wcnt[w][l] = __popc(mask);
        __syncthreads();
        if (tid <= T_) {
            int acc = 0;
            for (int ww = 0; ww < 32; ww++) {
                int c = wcnt[ww][tid];
                wcnt[ww][tid] = acc;
                acc += c;
            }
            tot[tid] = acc;
        }
        __syncthreads();
        if (tid == 0) {
            int a = 0;
            for (int b = T_; b >= 0; b--) { st[b] = a; a += tot[b]; }  // descending
        }
        __syncthreads();
        g_order[st[l] + wcnt[w][l] + rin] = tid;
    }

    int stride = gridDim.x * blockDim.x;
    int tid0   = blockIdx.x * blockDim.x + threadIdx.x;

    for (int idx = tid0; idx < NCPAD * NSLICE; idx += stride) {
        int j = idx / NSLICE, ks = idx % NSLICE;
        int k0 = ks * 16;
        float xs[16];
#pragma unroll
        for (int e = 0; e < 16; e++) {
            int k = k0 + e;
            float v = 0.f;
            if (j < NCOLS && k < KDIM)
                v = (j < G4H) ? Wih_f[(size_t)j * D_ + k]
                              : Wih_b[(size_t)(j - G4H) * D_ + k];
            xs[e] = v;
        }
        unsigned slots[8];
#pragma unroll
        for (int t = 0; t < 4; t++) {
            slots[2 * t]     = pack_h2(xs[2 * t],     xs[2 * t + 1]);
            slots[2 * t + 1] = pack_h2(xs[2 * t + 8], xs[2 * t + 9]);
        }
        unsigned* dst = &g_B16[(size_t)j * KP2 + ks * 8];
        *reinterpret_cast<uint4*>(dst)     = *reinterpret_cast<uint4*>(&slots[0]);
        *reinterpret_cast<uint4*>(dst + 4) = *reinterpret_cast<uint4*>(&slots[4]);
    }
    for (int idx = tid0; idx < 2 * H_ * H_; idx += stride) {
        int dir = idx / (H_ * H_);
        int rem = idx % (H_ * H_);
        int k = rem / H_, u = rem % H_;
        const float* Whh = dir ? Whh_b : Whh_f;
        float4 v;
        v.x = Whh[(size_t)(0 * H_ + u) * H_ + k];
        v.y = Whh[(size_t)(1 * H_ + u) * H_ + k];
        v.z = Whh[(size_t)(2 * H_ + u) * H_ + k];
        v.w = Whh[(size_t)(3 * H_ + u) * H_ + k];
        g_Wp[dir][k * H_ + u] = v;
    }
    for (int idx = tid0; idx < NCPAD; idx += stride) {
        float v = 0.f;
        if (idx < NCOLS) {
            int dir = idx / G4H, jj = idx % G4H;
            v = dir ? (bih_b[jj] + bhh_b[jj]) : (bih_f[jj] + bhh_f[jj]);
        }
        g_biasC[idx] = v;
    }
}

// ---------------------------------------------------------------------------
// Gather A -> fp16, slice-interleaved.
// ---------------------------------------------------------------------------
__global__ void gather_split(const float* __restrict__ hidden,
                             const int*   __restrict__ starts) {
    int idx = blockIdx.x * blockDim.x + threadIdx.x;
    int total = g_cnt * NSLICE;
    if (idx >= total) return;
    int m = idx / NSLICE, ks = idx % NSLICE;
    int k0 = ks * 16;
    float xs[16];
    if (k0 < KDIM) {
        int r = g_rows[m];
        int sp = r >> 5, t = r & 31;
        int b = sp >> 4, mm = sp & 15;
        int src = min(max(starts[b * MS_ + mm] + t, 0), S_ - 1);
        const float* base = &hidden[((size_t)b * S_ + src) * D_ + k0];
#pragma unroll
        for (int e = 0; e < 4; e++) {
            float4 v = *reinterpret_cast<const float4*>(base + 4 * e);
            xs[4 * e + 0] = v.x; xs[4 * e + 1] = v.y;
            xs[4 * e + 2] = v.z; xs[4 * e + 3] = v.w;
        }
    } else {
#pragma unroll
        for (int e = 0; e < 16; e++) xs[e] = 0.f;
    }
    unsigned slots[8];
#pragma unroll
    for (int t = 0; t < 4; t++) {
        slots[2 * t]     = pack_h2(xs[2 * t],     xs[2 * t + 1]);
        slots[2 * t + 1] = pack_h2(xs[2 * t + 8], xs[2 * t + 9]);
    }
    unsigned* dst = &g_A16[(size_t)m * KP2 + ks * 8];
    *reinterpret_cast<uint4*>(dst)     = *reinterpret_cast<uint4*>(&slots[0]);
    *reinterpret_cast<uint4*>(dst + 4) = *reinterpret_cast<uint4*>(&slots[4]);
}

// ---------------------------------------------------------------------------
// fp16 GEMM: 4 warps, 64x64 warp tile, cp.async double-buffered.
// Epilogue: bias + fp16 half2 scatter-store, gate-major (coalesced STG.32).
// ---------------------------------------------------------------------------
#define MMA_FP16(d, a, b)                                                       \
    asm volatile("mma.sync.aligned.m16n8k16.row.col.f32.f16.f16.f32 "           \
                 "{%0,%1,%2,%3}, {%4,%5,%6,%7}, {%8,%9}, {%0,%1,%2,%3};"        \
                 : "+f"(d[0]), "+f"(d[1]), "+f"(d[2]), "+f"(d[3])               \
                 : "r"(a[0]), "r"(a[1]), "r"(a[2]), "r"(a[3]),                  \
                   "r"(b[0]), "r"(b[1]));

__device__ __forceinline__ void cp16(unsigned* smem_ptr, const unsigned* gptr) {
    unsigned saddr = (unsigned)__cvta_generic_to_shared(smem_ptr);
    asm volatile("cp.async.cg.shared.global [%0], [%1], 16;" :: "r"(saddr), "l"(gptr));
}

#define MAT_TILE (128 * PITCH)          // 5120 u32
#define STG      (2 * MAT_TILE)         // 10240 u32/stage (40KB)

extern __shared__ unsigned smem_u[];

__global__ __launch_bounds__(128, 2) void gemm_tc(void) {
    const int cnt = g_cnt;
    const int m0  = blockIdx.y * 128;
    if (m0 >= cnt) return;
    const int n0  = blockIdx.x * 128;

    __shared__ int rowIdx[128];
    int tid = threadIdx.x;
    rowIdx[tid] = (m0 + tid < cnt) ? g_rows[m0 + tid] : -1;

    float acc[32][4];                     // mt(4) x nt(8)
#pragma unroll
    for (int i = 0; i < 32; i++)
#pragma unroll
        for (int q = 0; q < 4; q++) acc[i][q] = 0.f;

    int lane = tid & 31, wid = tid >> 5;  // 4 warps
    int wm = wid >> 1, wn = wid & 1;      // 2x2 warp grid
    int g = lane >> 2, tg = lane & 3;

    auto load_stage = [&](int stage, int k0u) {
        unsigned* As = smem_u + stage * STG;
        unsigned* Bs = As + MAT_TILE;
#pragma unroll
        for (int i = 0; i < 8; i++) {
            int id = tid + i * 128;
            int m = id >> 3, c = id & 7;
            cp16(&As[m * PITCH + c * 4], &g_A16[(size_t)(m0 + m) * KP2 + k0u + c * 4]);
        }
#pragma unroll
        for (int i = 0; i < 8; i++) {
            int id = tid + i * 128;
            int n = id >> 3, c = id & 7;
            cp16(&Bs[n * PITCH + c * 4], &g_B16[(size_t)(n0 + n) * KP2 + k0u + c * 4]);
        }
    };

    const int NITER = KP / KC;   // 13
    load_stage(0, 0);
    asm volatile("cp.async.commit_group;");

    for (int it = 0; it < NITER; it++) {
        if (it + 1 < NITER) load_stage((it + 1) & 1, (it + 1) * KC2);
        asm volatile("cp.async.commit_group;");
        asm volatile("cp.async.wait_group 1;");
        __syncthreads();

        const unsigned* As = smem_u + (it & 1) * STG;
        const unsigned* Bs = As + MAT_TILE;

#pragma unroll
        for (int ks = 0; ks < 4; ks++) {
            int kp = ks * 8;
            unsigned af[4][4];
#pragma unroll
            for (int mt = 0; mt < 4; mt++) {
                int r0 = wm * 64 + mt * 16 + g;
                ull v0 = *reinterpret_cast<const ull*>(As + r0 * PITCH + kp + 2 * tg);
                ull v1 = *reinterpret_cast<const ull*>(As + (r0 + 8) * PITCH + kp + 2 * tg);
                af[mt][0] = (unsigned)v0;
                af[mt][2] = (unsigned)(v0 >> 32);
                af[mt][1] = (unsigned)v1;
                af[mt][3] = (unsigned)(v1 >> 32);
            }
            unsigned bf[8][2];
#pragma unroll
            for (int nt = 0; nt < 8; nt++) {
                int c = wn * 64 + nt * 8 + g;
                ull v = *reinterpret_cast<const ull*>(Bs + c * PITCH + kp + 2 * tg);
                bf[nt][0] = (unsigned)v;
                bf[nt][1] = (unsigned)(v >> 32);
            }
#pragma unroll
            for (int mt = 0; mt < 4; mt++)
#pragma unroll
                for (int nt = 0; nt < 8; nt++)
                    MMA_FP16(acc[mt * 8 + nt], af[mt], bf[nt]);
        }
        __syncthreads();
    }

    // epilogue: bias + half2 scatter-store (gate-major cc = column index)
#pragma unroll
    for (int mt = 0; mt < 4; mt++) {
        int lr0 = wm * 64 + mt * 16 + g;
#pragma unroll
        for (int nt = 0; nt < 8; nt++) {
            int c = n0 + wn * 64 + nt * 8 + tg * 2;
            if (c >= NCOLS) continue;
            float* a = acc[mt * 8 + nt];
            float2 bias = *reinterpret_cast<const float2*>(&g_biasC[c]);
            int dirb = (c >= G4H);
            int cc   = c - dirb * G4H;
#pragma unroll
            for (int h = 0; h < 2; h++) {
                int lr = lr0 + h * 8;
                if (m0 + lr < cnt) {
                    int rid = rowIdx[lr];
                    unsigned hv = pack_h2(a[h * 2 + 0] + bias.x, a[h * 2 + 1] + bias.y);
                    *reinterpret_cast<unsigned*>(&g_Zh[dirb][(size_t)rid * G4H + cc]) = hv;
                }
            }
        }
    }
}

// ---------------------------------------------------------------------------
// Recurrence: 448 threads per CTA, both directions as independent halves
// (warps 0-6 fwd, 7-13 bwd) over the SAME 8-span group -> identical step
// counts, named-barrier sync per half, 128 CTAs = single wave on 148 SMs.
// ---------------------------------------------------------------------------
__device__ __forceinline__ float fast_sig(float x)  { return 1.f / (1.f + __expf(-x)); }
__device__ __forceinline__ float fast_tanh(float x) {
    float t = __expf(-2.f * x);
    return __fdividef(1.f - t, 1.f + t);
}

__global__ __launch_bounds__(448) void lstm_kernel(const int* __restrict__ span_lens) {
    __shared__ float4 h4[2][2][PSPAN][H_ / 4];   // [dir][buf][span][k4]
    __shared__ int    sp_sh[PSPAN];
    __shared__ int    len_sh[PSPAN];

    int tid = threadIdx.x;
    int dir = (tid >= 224) ? 1 : 0;
    int u   = tid - dir * 224;
    bool act = u < H_;
    int n0  = blockIdx.x * PSPAN;

    if (tid < PSPAN) {
        int sp = g_order[n0 + tid];
        sp_sh[tid]  = sp;
        len_sh[tid] = min(max(span_lens[sp], 0), T_);
    }
    {
        float* hz = (float*)h4;
        for (int i = tid; i < 2 * 2 * PSPAN * H_; i += 448) hz[i] = 0.f;
    }
    __syncthreads();

    int maxL = 0;
#pragma unroll
    for (int p = 0; p < PSPAN; p++) maxL = max(maxL, len_sh[p]);

    const __half*  Zh = g_Zh[dir];
    const float4*  Wp = g_Wp[dir];
    const int      bar = dir + 1;

    float c[PSPAN], feat[PSPAN], hreg[PSPAN];
#pragma unroll
    for (int p = 0; p < PSPAN; p++) { c[p] = 0.f; feat[p] = 0.f; hreg[p] = 0.f; }

    int buf = 0;
    for (int s = 0; s < maxL; s++) {
        float a0[PSPAN], a1[PSPAN], a2[PSPAN], a3[PSPAN];
        if (act) {
#pragma unroll
            for (int p = 0; p < PSPAN; p++) {
                int L = len_sh[p];
                int t = dir ? (L - 1 - s) : s;
                if (s >= L) t = 0;
                const __half* zr = Zh + ((size_t)sp_sh[p] * T_ + t) * G4H;
                a0[p] = __half2float(zr[u]);
                a1[p] = __half2float(zr[H_ + u]);
                a2[p] = __half2float(zr[2 * H_ + u]);
                a3[p] = __half2float(zr[3 * H_ + u]);
            }
#pragma unroll 2
            for (int k = 0; k < H_; k += 4) {
                float4 w0 = Wp[(k + 0) * H_ + u];
                float4 w1 = Wp[(k + 1) * H_ + u];
                float4 w2 = Wp[(k + 2) * H_ + u];
                float4 w3 = Wp[(k + 3) * H_ + u];
#pragma unroll
                for (int p = 0; p < PSPAN; p++) {
                    float4 hv = h4[dir][buf][p][k >> 2];
                    a0[p] += w0.x * hv.x; a0[p] += w1.x * hv.y;
                    a0[p] += w2.x * hv.z; a0[p] += w3.x * hv.w;
                    a1[p] += w0.y * hv.x; a1[p] += w1.y * hv.y;
                    a1[p] += w2.y * hv.z; a1[p] += w3.y * hv.w;
                    a2[p] += w0.z * hv.x; a2[p] += w1.z * hv.y;
                    a2[p] += w2.z * hv.z; a2[p] += w3.z * hv.w;
                    a3[p] += w0.w * hv.x; a3[p] += w1.w * hv.y;
                    a3[p] += w2.w * hv.z; a3[p] += w3.w * hv.w;
                }
            }
#pragma unroll
            for (int p = 0; p < PSPAN; p++) {
                if (s < len_sh[p]) {
                    float ig = fast_sig(a0[p]);
                    float fg = fast_sig(a1[p]);
                    float gg = fast_tanh(a2[p]);
                    float og = fast_sig(a3[p]);
                    float cn = fg * c[p] + ig * gg;
                    c[p] = cn;
                    hreg[p] = og * fast_tanh(cn);
                    feat[p] += hreg[p];
                }
                ((float*)&h4[dir][buf ^ 1][p][0])[u] = hreg[p];
            }
        }
        asm volatile("bar.sync %0, %1;" :: "r"(bar), "r"(224) : "memory");
        buf ^= 1;
    }

    if (act) {
#pragma unroll
        for (int p = 0; p < PSPAN; p++)
            g_feats[(size_t)sp_sh[p] * (2 * H_) + dir * H_ + u] = feat[p];
    }
}

// ---------------------------------------------------------------------------
// logits
// ---------------------------------------------------------------------------
__global__ __launch_bounds__(192) void logits_kernel(const float* __restrict__ slot_embs,
                                                     const float* __restrict__ slot_mask,
                                                     float* __restrict__ out) {
    __shared__ float f_sm[16][2 * H_];
    __shared__ float se_sm[2 * H_ * NS_];

    int tid = threadIdx.x;
    int n0  = blockIdx.x * 16;

    for (int i = tid; i < 2 * H_ * NS_; i += blockDim.x) se_sm[i] = slot_embs[i];
    for (int i = tid; i < 16 * 2 * H_; i += blockDim.x) {
        int sp = i / (2 * H_), h = i % (2 * H_);
        f_sm[sp][h] = g_feats[(size_t)(n0 + sp) * (2 * H_) + h];
    }
    __syncthreads();

    int sp = tid / NS_, ns = tid % NS_;
    float acc = 0.f;
#pragma unroll 8
    for (int h = 0; h < 2 * H_; h++) acc += f_sm[sp][h] * se_sm[h * NS_ + ns];
    out[(n0 + sp) * NS_ + ns] = acc * slot_mask[n0 + sp];
}

// ---------------------------------------------------------------------------
extern "C" void kernel_launch(void* const* d_in, const int* in_sizes, int n_in,
                              void* d_out, int out_size) {
    const float* hidden    = (const float*)d_in[0];
    const float* Wih_f     = (const float*)d_in[1];
    const float* Whh_f     = (const float*)d_in[2];
    const float* bih_f     = (const float*)d_in[3];
    const float* bhh_f     = (const float*)d_in[4];
    const float* Wih_b     = (const float*)d_in[5];
    const float* Whh_b     = (const float*)d_in[6];
    const float* bih_b     = (const float*)d_in[7];
    const float* bhh_b     = (const float*)d_in[8];
    const float* slot_embs = (const float*)d_in[9];
    const int*   starts    = (const int*)d_in[10];
    const int*   lens      = (const int*)d_in[11];
    const float* slot_mask = (const float*)d_in[12];
    float* out = (float*)d_out;

    const int gemm_smem = 2 * STG * (int)sizeof(unsigned);   // 81920 B
    cudaFuncSetAttribute(gemm_tc, cudaFuncAttributeMaxDynamicSharedMemorySize, gemm_smem);

    // lstm stays the 4th launch -> lands in ncu's profile window
    packprep_kernel<<<256, 1024>>>(Wih_f, Whh_f, bih_f, bhh_f,
                                   Wih_b, Whh_b, bih_b, bhh_b, lens);

    gather_split<<<(MROWS * NSLICE + 255) / 256, 256>>>(hidden, starts);

    dim3 ggrid(NCPAD / 128, MROWS / 128);
    gemm_tc<<<ggrid, 128, gemm_smem>>>();

    lstm_kernel<<<128, 448>>>(lens);   // one group per CTA, both dirs inside

    logits_kernel<<<NSPAN / 16, 192>>>(slot_embs, slot_mask, out);
}

// round 12
// speedup vs baseline: 1.1526x; 1.1228x over previous
#include <cuda_runtime.h>
#include <cuda_fp16.h>
#include <math.h>

#define B_    64
#define S_    1024
#define D_    800
#define MS_   16
#define T_    32
#define H_    200
#define NS_   12
#define NSPAN (B_*MS_)        // 1024
#define MROWS (NSPAN*T_)      // 32768
#define KDIM  D_              // 800
#define KP    832             // GEMM K padded (52 k-slices of 16)
#define KP2   (KP/2)          // 416 u32 per row
#define NSLICE (KP/16)        // 52
#define G4H   (4*H_)          // 800
#define NCOLS 1600
#define NCPAD 1664
#define PSPAN 4               // spans per LSTM CTA (fine-grained for balance)
#define KC    64
#define KC2   (KC/2)
#define PITCH 40              // GEMM smem pitch (u32): LDS.64 conflict-free

typedef unsigned long long ull;

// -------- scratch (static device arrays; no runtime alloc) ------------------
__device__ __half   g_Zh[2][(size_t)MROWS * G4H];  // fp16 Z, gate-major [row][gate*200+u]
__device__ unsigned g_A16[(size_t)MROWS * KP2];    // gathered A fp16, slice-interleaved
__device__ unsigned g_B16[(size_t)NCPAD * KP2];    // Wih^T n-major fp16, slice-interleaved
__device__ float4   g_Wp[2][H_ * H_];              // recurrent weights [dir][k*H+u]
__device__ float    g_biasC[NCPAD];
__device__ float    g_feats[(size_t)NSPAN * 2 * H_];
__device__ int      g_rows[MROWS];
__device__ int      g_order[NSPAN];
__device__ int      g_cnt;

__device__ __forceinline__ unsigned pack_h2(float x0, float x1) {
    __half2 h = __floats2half2_rn(x0, x1);
    return *reinterpret_cast<unsigned*>(&h);
}

// slice interleave: slot 2t = kpair t, slot 2t+1 = kpair t+4  (t = 0..3)

// ---------------------------------------------------------------------------
// Fused pack + prep. Block 0 runs the prefix-scan and descending counting
// sort; all blocks pack Wih^T -> fp16 slice-interleaved, Whh, biases.
// ---------------------------------------------------------------------------
__global__ __launch_bounds__(1024) void packprep_kernel(
        const float* __restrict__ Wih_f, const float* __restrict__ Whh_f,
        const float* __restrict__ bih_f, const float* __restrict__ bhh_f,
        const float* __restrict__ Wih_b, const float* __restrict__ Whh_b,
        const float* __restrict__ bih_b, const float* __restrict__ bhh_b,
        const int*   __restrict__ lens) {
    if (blockIdx.x == 0) {
        __shared__ int s[NSPAN];
        __shared__ int wcnt[32][T_ + 1];
        __shared__ int st[T_ + 1];
        __shared__ int tot[T_ + 1];
        int tid = threadIdx.x;
        int lane = tid & 31, w = tid >> 5;
        int l = min(max(lens[tid], 0), T_);
        s[tid] = l;
        for (int b = lane; b <= T_; b += 32) wcnt[w][b] = 0;
        __syncthreads();
        for (int d = 1; d < NSPAN; d <<= 1) {
            int v = (tid >= d) ? s[tid - d] : 0;
            __syncthreads();
            s[tid] += v;
            __syncthreads();
        }
        int off = s[tid] - l;
        for (int t = 0; t < l; t++) g_rows[off + t] = tid * T_ + t;
        if (tid == NSPAN - 1) g_cnt = s[tid];

        unsigned mask = __match_any_sync(0xffffffffu, l);
        int rin = __popc(mask & ((1u << lane) - 1u));
        if (rin == 0) wcnt[w][l] = __popc(mask);
        __syncthreads();
        if (tid <= T_) {
            int acc = 0;
            for (int ww = 0; ww < 32; ww++) {
                int c = wcnt[ww][tid];
                wcnt[ww][tid] = acc;
                acc += c;
            }
            tot[tid] = acc;
        }
        __syncthreads();
        if (tid == 0) {
            int a = 0;
            for (int b = T_; b >= 0; b--) { st[b] = a; a += tot[b]; }  // descending
        }
        __syncthreads();
        g_order[st[l] + wcnt[w][l] + rin] = tid;
    }

    int stride = gridDim.x * blockDim.x;
    int tid0   = blockIdx.x * blockDim.x + threadIdx.x;

    for (int idx = tid0; idx < NCPAD * NSLICE; idx += stride) {
        int j = idx / NSLICE, ks = idx % NSLICE;
        int k0 = ks * 16;
        float xs[16];
#pragma unroll
        for (int e = 0; e < 16; e++) {
            int k = k0 + e;
            float v = 0.f;
            if (j < NCOLS && k < KDIM)
                v = (j < G4H) ? Wih_f[(size_t)j * D_ + k]
                              : Wih_b[(size_t)(j - G4H) * D_ + k];
            xs[e] = v;
        }
        unsigned slots[8];
#pragma unroll
        for (int t = 0; t < 4; t++) {
            slots[2 * t]     = pack_h2(xs[2 * t],     xs[2 * t + 1]);
            slots[2 * t + 1] = pack_h2(xs[2 * t + 8], xs[2 * t + 9]);
        }
        unsigned* dst = &g_B16[(size_t)j * KP2 + ks * 8];
        *reinterpret_cast<uint4*>(dst)     = *reinterpret_cast<uint4*>(&slots[0]);
        *reinterpret_cast<uint4*>(dst + 4) = *reinterpret_cast<uint4*>(&slots[4]);
    }
    for (int idx = tid0; idx < 2 * H_ * H_; idx += stride) {
        int dir = idx / (H_ * H_);
        int rem = idx % (H_ * H_);
        int k = rem / H_, u = rem % H_;
        const float* Whh = dir ? Whh_b : Whh_f;
        float4 v;
        v.x = Whh[(size_t)(0 * H_ + u) * H_ + k];
        v.y = Whh[(size_t)(1 * H_ + u) * H_ + k];
        v.z = Whh[(size_t)(2 * H_ + u) * H_ + k];
        v.w = Whh[(size_t)(3 * H_ + u) * H_ + k];
        g_Wp[dir][k * H_ + u] = v;
    }
    for (int idx = tid0; idx < NCPAD; idx += stride) {
        float v = 0.f;
        if (idx < NCOLS) {
            int dir = idx / G4H, jj = idx % G4H;
            v = dir ? (bih_b[jj] + bhh_b[jj]) : (bih_f[jj] + bhh_f[jj]);
        }
        g_biasC[idx] = v;
    }
}

// ---------------------------------------------------------------------------
// Gather A -> fp16, slice-interleaved.
// ---------------------------------------------------------------------------
__global__ void gather_split(const float* __restrict__ hidden,
                             const int*   __restrict__ starts) {
    int idx = blockIdx.x * blockDim.x + threadIdx.x;
    int total = g_cnt * NSLICE;
    if (idx >= total) return;
    int m = idx / NSLICE, ks = idx % NSLICE;
    int k0 = ks * 16;
    float xs[16];
    if (k0 < KDIM) {
        int r = g_rows[m];
        int sp = r >> 5, t = r & 31;
        int b = sp >> 4, mm = sp & 15;
        int src = min(max(starts[b * MS_ + mm] + t, 0), S_ - 1);
        const float* base = &hidden[((size_t)b * S_ + src) * D_ + k0];
#pragma unroll
        for (int e = 0; e < 4; e++) {
            float4 v = *reinterpret_cast<const float4*>(base + 4 * e);
            xs[4 * e + 0] = v.x; xs[4 * e + 1] = v.y;
            xs[4 * e + 2] = v.z; xs[4 * e + 3] = v.w;
        }
    } else {
#pragma unroll
        for (int e = 0; e < 16; e++) xs[e] = 0.f;
    }
    unsigned slots[8];
#pragma unroll
    for (int t = 0; t < 4; t++) {
        slots[2 * t]     = pack_h2(xs[2 * t],     xs[2 * t + 1]);
        slots[2 * t + 1] = pack_h2(xs[2 * t + 8], xs[2 * t + 9]);
    }
    unsigned* dst = &g_A16[(size_t)m * KP2 + ks * 8];
    *reinterpret_cast<uint4*>(dst)     = *reinterpret_cast<uint4*>(&slots[0]);
    *reinterpret_cast<uint4*>(dst + 4) = *reinterpret_cast<uint4*>(&slots[4]);
}

// ---------------------------------------------------------------------------
// fp16 GEMM: 4 warps, 64x64 warp tile, cp.async double-buffered.
// ---------------------------------------------------------------------------
#define MMA_FP16(d, a, b)                                                       \
    asm volatile("mma.sync.aligned.m16n8k16.row.col.f32.f16.f16.f32 "           \
                 "{%0,%1,%2,%3}, {%4,%5,%6,%7}, {%8,%9}, {%0,%1,%2,%3};"        \
                 : "+f"(d[0]), "+f"(d[1]), "+f"(d[2]), "+f"(d[3])               \
                 : "r"(a[0]), "r"(a[1]), "r"(a[2]), "r"(a[3]),                  \
                   "r"(b[0]), "r"(b[1]));

__device__ __forceinline__ void cp16(unsigned* smem_ptr, const unsigned* gptr) {
    unsigned saddr = (unsigned)__cvta_generic_to_shared(smem_ptr);
    asm volatile("cp.async.cg.shared.global [%0], [%1], 16;" :: "r"(saddr), "l"(gptr));
}

#define MAT_TILE (128 * PITCH)          // 5120 u32
#define STG      (2 * MAT_TILE)         // 10240 u32/stage (40KB)

extern __shared__ unsigned smem_u[];

__global__ __launch_bounds__(128, 2) void gemm_tc(void) {
    const int cnt = g_cnt;
    const int m0  = blockIdx.y * 128;
    if (m0 >= cnt) return;
    const int n0  = blockIdx.x * 128;

    __shared__ int rowIdx[128];
    int tid = threadIdx.x;
    rowIdx[tid] = (m0 + tid < cnt) ? g_rows[m0 + tid] : -1;

    float acc[32][4];                     // mt(4) x nt(8)
#pragma unroll
    for (int i = 0; i < 32; i++)
#pragma unroll
        for (int q = 0; q < 4; q++) acc[i][q] = 0.f;

    int lane = tid & 31, wid = tid >> 5;  // 4 warps
    int wm = wid >> 1, wn = wid & 1;      // 2x2 warp grid
    int g = lane >> 2, tg = lane & 3;

    auto load_stage = [&](int stage, int k0u) {
        unsigned* As = smem_u + stage * STG;
        unsigned* Bs = As + MAT_TILE;
#pragma unroll
        for (int i = 0; i < 8; i++) {
            int id = tid + i * 128;
            int m = id >> 3, c = id & 7;
            cp16(&As[m * PITCH + c * 4], &g_A16[(size_t)(m0 + m) * KP2 + k0u + c * 4]);
        }
#pragma unroll
        for (int i = 0; i < 8; i++) {
            int id = tid + i * 128;
            int n = id >> 3, c = id & 7;
            cp16(&Bs[n * PITCH + c * 4], &g_B16[(size_t)(n0 + n) * KP2 + k0u + c * 4]);
        }
    };

    const int NITER = KP / KC;   // 13
    load_stage(0, 0);
    asm volatile("cp.async.commit_group;");

    for (int it = 0; it < NITER; it++) {
        if (it + 1 < NITER) load_stage((it + 1) & 1, (it + 1) * KC2);
        asm volatile("cp.async.commit_group;");
        asm volatile("cp.async.wait_group 1;");
        __syncthreads();

        const unsigned* As = smem_u + (it & 1) * STG;
        const unsigned* Bs = As + MAT_TILE;

#pragma unroll
        for (int ks = 0; ks < 4; ks++) {
            int kp = ks * 8;
            unsigned af[4][4];
#pragma unroll
            for (int mt = 0; mt < 4; mt++) {
                int r0 = wm * 64 + mt * 16 + g;
                ull v0 = *reinterpret_cast<const ull*>(As + r0 * PITCH + kp + 2 * tg);
                ull v1 = *reinterpret_cast<const ull*>(As + (r0 + 8) * PITCH + kp + 2 * tg);
                af[mt][0] = (unsigned)v0;
                af[mt][2] = (unsigned)(v0 >> 32);
                af[mt][1] = (unsigned)v1;
                af[mt][3] = (unsigned)(v1 >> 32);
            }
            unsigned bf[8][2];
#pragma unroll
            for (int nt = 0; nt < 8; nt++) {
                int c = wn * 64 + nt * 8 + g;
                ull v = *reinterpret_cast<const ull*>(Bs + c * PITCH + kp + 2 * tg);
                bf[nt][0] = (unsigned)v;
                bf[nt][1] = (unsigned)(v >> 32);
            }
#pragma unroll
            for (int mt = 0; mt < 4; mt++)
#pragma unroll
                for (int nt = 0; nt < 8; nt++)
                    MMA_FP16(acc[mt * 8 + nt], af[mt], bf[nt]);
        }
        __syncthreads();
    }

    // epilogue: bias + half2 scatter-store (gate-major)
#pragma unroll
    for (int mt = 0; mt < 4; mt++) {
        int lr0 = wm * 64 + mt * 16 + g;
#pragma unroll
        for (int nt = 0; nt < 8; nt++) {
            int c = n0 + wn * 64 + nt * 8 + tg * 2;
            if (c >= NCOLS) continue;
            float* a = acc[mt * 8 + nt];
            float2 bias = *reinterpret_cast<const float2*>(&g_biasC[c]);
            int dirb = (c >= G4H);
            int cc   = c - dirb * G4H;
#pragma unroll
            for (int h = 0; h < 2; h++) {
                int lr = lr0 + h * 8;
                if (m0 + lr < cnt) {
                    int rid = rowIdx[lr];
                    unsigned hv = pack_h2(a[h * 2 + 0] + bias.x, a[h * 2 + 1] + bias.y);
                    *reinterpret_cast<unsigned*>(&g_Zh[dirb][(size_t)rid * G4H + cc]) = hv;
                }
            }
        }
    }
}

// ---------------------------------------------------------------------------
// Recurrence: 4 spans per CTA, one direction, 224 threads (7 warps).
// 512 CTAs descending by group length -> LPT balance via wave>=2
// work-stealing; ~3.5 co-resident CTAs/SM keep FFMA issue saturated.
// ---------------------------------------------------------------------------
__device__ __forceinline__ float fast_sig(float x)  { return 1.f / (1.f + __expf(-x)); }
__device__ __forceinline__ float fast_tanh(float x) {
    float t = __expf(-2.f * x);
    return __fdividef(1.f - t, 1.f + t);
}

__global__ __launch_bounds__(224) void lstm_kernel(const int* __restrict__ span_lens) {
    __shared__ float4 h4[2][PSPAN][H_ / 4];
    __shared__ int    sp_sh[PSPAN];
    __shared__ int    len_sh[PSPAN];

    int tid = threadIdx.x;
    int dir = blockIdx.y;
    int u   = tid;
    bool act = u < H_;
    int n0  = blockIdx.x * PSPAN;

    const __half* Zh = g_Zh[dir];
    const float4* Wp = g_Wp[dir];

    if (tid < PSPAN) {
        int sp = g_order[n0 + tid];
        sp_sh[tid]  = sp;
        len_sh[tid] = min(max(span_lens[sp], 0), T_);
    }
    {
        float* hz = (float*)h4;
        for (int i = tid; i < 2 * PSPAN * H_; i += 224) hz[i] = 0.f;
    }
    __syncthreads();

    int maxL = 0;
#pragma unroll
    for (int p = 0; p < PSPAN; p++) maxL = max(maxL, len_sh[p]);

    float c[PSPAN], feat[PSPAN], hreg[PSPAN];
#pragma unroll
    for (int p = 0; p < PSPAN; p++) { c[p] = 0.f; feat[p] = 0.f; hreg[p] = 0.f; }

    int buf = 0;
    for (int s = 0; s < maxL; s++) {
        float a0[PSPAN], a1[PSPAN], a2[PSPAN], a3[PSPAN];
        if (act) {
#pragma unroll
            for (int p = 0; p < PSPAN; p++) {
                int L = len_sh[p];
                int t = dir ? (L - 1 - s) : s;
                if (s >= L) t = 0;
                const __half* zr = Zh + ((size_t)sp_sh[p] * T_ + t) * G4H;
                a0[p] = __half2float(zr[u]);
                a1[p] = __half2float(zr[H_ + u]);
                a2[p] = __half2float(zr[2 * H_ + u]);
                a3[p] = __half2float(zr[3 * H_ + u]);
            }
#pragma unroll 2
            for (int k = 0; k < H_; k += 4) {
                float4 w0 = Wp[(k + 0) * H_ + u];
                float4 w1 = Wp[(k + 1) * H_ + u];
                float4 w2 = Wp[(k + 2) * H_ + u];
                float4 w3 = Wp[(k + 3) * H_ + u];
#pragma unroll
                for (int p = 0; p < PSPAN; p++) {
                    float4 hv = h4[buf][p][k >> 2];
                    a0[p] += w0.x * hv.x; a0[p] += w1.x * hv.y;
                    a0[p] += w2.x * hv.z; a0[p] += w3.x * hv.w;
                    a1[p] += w0.y * hv.x; a1[p] += w1.y * hv.y;
                    a1[p] += w2.y * hv.z; a1[p] += w3.y * hv.w;
                    a2[p] += w0.z * hv.x; a2[p] += w1.z * hv.y;
                    a2[p] += w2.z * hv.z; a2[p] += w3.z * hv.w;
                    a3[p] += w0.w * hv.x; a3[p] += w1.w * hv.y;
                    a3[p] += w2.w * hv.z; a3[p] += w3.w * hv.w;
                }
            }
#pragma unroll
            for (int p = 0; p < PSPAN; p++) {
                if (s < len_sh[p]) {
                    float ig = fast_sig(a0[p]);
                    float fg = fast_sig(a1[p]);
                    float gg = fast_tanh(a2[p]);
                    float og = fast_sig(a3[p]);
                    float cn = fg * c[p] + ig * gg;
                    c[p] = cn;
                    hreg[p] = og * fast_tanh(cn);
                    feat[p] += hreg[p];
                }
                ((float*)&h4[buf ^ 1][p][0])[u] = hreg[p];
            }
        }
        __syncthreads();
        buf ^= 1;
    }

    if (act) {
#pragma unroll
        for (int p = 0; p < PSPAN; p++)
            g_feats[(size_t)sp_sh[p] * (2 * H_) + dir * H_ + u] = feat[p];
    }
}

// ---------------------------------------------------------------------------
// logits
// ---------------------------------------------------------------------------
__global__ __launch_bounds__(192) void logits_kernel(const float* __restrict__ slot_embs,
                                                     const float* __restrict__ slot_mask,
                                                     float* __restrict__ out) {
    __shared__ float f_sm[16][2 * H_];
    __shared__ float se_sm[2 * H_ * NS_];

    int tid = threadIdx.x;
    int n0  = blockIdx.x * 16;

    for (int i = tid; i < 2 * H_ * NS_; i += blockDim.x) se_sm[i] = slot_embs[i];
    for (int i = tid; i < 16 * 2 * H_; i += blockDim.x) {
        int sp = i / (2 * H_), h = i % (2 * H_);
        f_sm[sp][h] = g_feats[(size_t)(n0 + sp) * (2 * H_) + h];
    }
    __syncthreads();

    int sp = tid / NS_, ns = tid % NS_;
    float acc = 0.f;
#pragma unroll 8
    for (int h = 0; h < 2 * H_; h++) acc += f_sm[sp][h] * se_sm[h * NS_ + ns];
    out[(n0 + sp) * NS_ + ns] = acc * slot_mask[n0 + sp];
}

// ---------------------------------------------------------------------------
extern "C" void kernel_launch(void* const* d_in, const int* in_sizes, int n_in,
                              void* d_out, int out_size) {
    const float* hidden    = (const float*)d_in[0];
    const float* Wih_f     = (const float*)d_in[1];
    const float* Whh_f     = (const float*)d_in[2];
    const float* bih_f     = (const float*)d_in[3];
    const float* bhh_f     = (const float*)d_in[4];
    const float* Wih_b     = (const float*)d_in[5];
    const float* Whh_b     = (const float*)d_in[6];
    const float* bih_b     = (const float*)d_in[7];
    const float* bhh_b     = (const float*)d_in[8];
    const float* slot_embs = (const float*)d_in[9];
    const int*   starts    = (const int*)d_in[10];
    const int*   lens      = (const int*)d_in[11];
    const float* slot_mask = (const float*)d_in[12];
    float* out = (float*)d_out;

    const int gemm_smem = 2 * STG * (int)sizeof(unsigned);   // 81920 B
    cudaFuncSetAttribute(gemm_tc, cudaFuncAttributeMaxDynamicSharedMemorySize, gemm_smem);

    // lstm stays the 4th launch -> lands in ncu's profile window
    packprep_kernel<<<256, 1024>>>(Wih_f, Whh_f, bih_f, bhh_f,
                                   Wih_b, Whh_b, bih_b, bhh_b, lens);

    gather_split<<<(MROWS * NSLICE + 255) / 256, 256>>>(hidden, starts);

    dim3 ggrid(NCPAD / 128, MROWS / 128);
    gemm_tc<<<ggrid, 128, gemm_smem>>>();

    dim3 lgrid(NSPAN / PSPAN, 2);   // 512 CTAs, 4 descending-length spans each
    lstm_kernel<<<lgrid, 224>>>(lens);

    logits_kernel<<<NSPAN / 16, 192>>>(slot_embs, slot_mask, out);
}

// round 14
// speedup vs baseline: 1.5297x; 1.3271x over previous
#include <cuda_runtime.h>
#include <cuda_fp16.h>
#include <math.h>

#define B_    64
#define S_    1024
#define D_    800
#define MS_   16
#define T_    32
#define H_    200
#define NS_   12
#define NSPAN (B_*MS_)        // 1024
#define MROWS (NSPAN*T_)      // 32768
#define KDIM  D_              // 800
#define KP    832             // GEMM K padded (52 k-slices of 16)
#define KP2   (KP/2)          // 416 u32 per row
#define NSLICE (KP/16)        // 52
#define G4H   (4*H_)          // 800
#define NCOLS 1600
#define NCPAD 1664
#define PSPAN 4               // spans per LSTM CTA
#define KC    64
#define KC2   (KC/2)
#define PITCH 40              // GEMM smem pitch (u32): LDS.64 conflict-free
#define NCHK  50              // 200 k / 4 per chunk

typedef unsigned long long ull;

// -------- scratch (static device arrays; no runtime alloc) ------------------
__device__ __half   g_Zh[2][(size_t)MROWS * G4H];  // fp16 Z, gate-major [row][gate*200+u]
__device__ unsigned g_A16[(size_t)MROWS * KP2];    // gathered A fp16, slice-interleaved
__device__ unsigned g_B16[(size_t)NCPAD * KP2];    // Wih^T n-major fp16, slice-interleaved
__device__ float4   g_Wq[2][4][NCHK][H_];          // Whh k-paired: [dir][gate][kchunk][u] = (w_k0..w_k3)
__device__ float    g_biasC[NCPAD];
__device__ float    g_feats[(size_t)NSPAN * 2 * H_];
__device__ int      g_rows[MROWS];
__device__ int      g_order[NSPAN];
__device__ int      g_cnt;

__device__ __forceinline__ unsigned pack_h2(float x0, float x1) {
    __half2 h = __floats2half2_rn(x0, x1);
    return *reinterpret_cast<unsigned*>(&h);
}

#define FMA_X2(d, a, b) \
    asm("fma.rn.f32x2 %0, %1, %2, %0;" : "+l"(d) : "l"(a), "l"(b))

// slice interleave: slot 2t = kpair t, slot 2t+1 = kpair t+4  (t = 0..3)

// ---------------------------------------------------------------------------
// Fused pack + prep. Block 0 runs the prefix-scan and descending counting
// sort; all blocks pack Wih^T (fp16 slice-interleaved), Whh (k-paired), biases.
// ---------------------------------------------------------------------------
__global__ __launch_bounds__(1024) void packprep_kernel(
        const float* __restrict__ Wih_f, const float* __restrict__ Whh_f,
        const float* __restrict__ bih_f, const float* __restrict__ bhh_f,
        const float* __restrict__ Wih_b, const float* __restrict__ Whh_b,
        const float* __restrict__ bih_b, const float* __restrict__ bhh_b,
        const int*   __restrict__ lens) {
    if (blockIdx.x == 0) {
        __shared__ int s[NSPAN];
        __shared__ int wcnt[32][T_ + 1];
        __shared__ int st[T_ + 1];
        __shared__ int tot[T_ + 1];
        int tid = threadIdx.x;
        int lane = tid & 31, w = tid >> 5;
        int l = min(max(lens[tid], 0), T_);
        s[tid] = l;
        for (int b = lane; b <= T_; b += 32) wcnt[w][b] = 0;
        __syncthreads();
        for (int d = 1; d < NSPAN; d <<= 1) {
            int v = (tid >= d) ? s[tid - d] : 0;
            __syncthreads();
            s[tid] += v;
            __syncthreads();
        }
        int off = s[tid] - l;
        for (int t = 0; t < l; t++) g_rows[off + t] = tid * T_ + t;
        if (tid == NSPAN - 1) g_cnt = s[tid];

        unsigned mask = __match_any_sync(0xffffffffu, l);
        int rin = __popc(mask & ((1u << lane) - 1u));
        if (rin == 0) wcnt[w][l] = __popc(mask);
        __syncthreads();
        if (tid <= T_) {
            int acc = 0;
            for (int ww = 0; ww < 32; ww++) {
                int c = wcnt[ww][tid];
                wcnt[ww][tid] = acc;
                acc += c;
            }
            tot[tid] = acc;
        }
        __syncthreads();
        if (tid == 0) {
            int a = 0;
            for (int b = T_; b >= 0; b--) { st[b] = a; a += tot[b]; }  // descending
        }
        __syncthreads();
        g_order[st[l] + wcnt[w][l] + rin] = tid;
    }

    int stride = gridDim.x * blockDim.x;
    int tid0   = blockIdx.x * blockDim.x + threadIdx.x;

    for (int idx = tid0; idx < NCPAD * NSLICE; idx += stride) {
        int j = idx / NSLICE, ks = idx % NSLICE;
        int k0 = ks * 16;
        float xs[16];
#pragma unroll
        for (int e = 0; e < 16; e++) {
            int k = k0 + e;
            float v = 0.f;
            if (j < NCOLS && k < KDIM)
                v = (j < G4H) ? Wih_f[(size_t)j * D_ + k]
                              : Wih_b[(size_t)(j - G4H) * D_ + k];
            xs[e] = v;
        }
        unsigned slots[8];
#pragma unroll
        for (int t = 0; t < 4; t++) {
            slots[2 * t]     = pack_h2(xs[2 * t],     xs[2 * t + 1]);
            slots[2 * t + 1] = pack_h2(xs[2 * t + 8], xs[2 * t + 9]);
        }
        unsigned* dst = &g_B16[(size_t)j * KP2 + ks * 8];
        *reinterpret_cast<uint4*>(dst)     = *reinterpret_cast<uint4*>(&slots[0]);
        *reinterpret_cast<uint4*>(dst + 4) = *reinterpret_cast<uint4*>(&slots[4]);
    }
    // Whh k-paired pack: [dir][gate][chunk c][u] = (w[g*H+u][4c..4c+3])
    for (int idx = tid0; idx < 2 * 4 * NCHK * H_; idx += stride) {
        int u  = idx % H_;
        int c  = (idx / H_) % NCHK;
        int gt = (idx / (H_ * NCHK)) % 4;
        int dir = idx / (H_ * NCHK * 4);
        const float* Whh = dir ? Whh_b : Whh_f;
        const float* row = &Whh[(size_t)(gt * H_ + u) * H_ + 4 * c];
        float4 v;
        v.x = row[0]; v.y = row[1]; v.z = row[2]; v.w = row[3];
        g_Wq[dir][gt][c][u] = v;
    }
    for (int idx = tid0; idx < NCPAD; idx += stride) {
        float v = 0.f;
        if (idx < NCOLS) {
            int dir = idx / G4H, jj = idx % G4H;
            v = dir ? (bih_b[jj] + bhh_b[jj]) : (bih_f[jj] + bhh_f[jj]);
        }
        g_biasC[idx] = v;
    }
}

// ---------------------------------------------------------------------------
// Gather A -> fp16, slice-interleaved.
// ---------------------------------------------------------------------------
__global__ void gather_split(const float* __restrict__ hidden,
                             const int*   __restrict__ starts) {
    int idx = blockIdx.x * blockDim.x + threadIdx.x;
    int total = g_cnt * NSLICE;
    if (idx >= total) return;
    int m = idx / NSLICE, ks = idx % NSLICE;
    int k0 = ks * 16;
    float xs[16];
    if (k0 < KDIM) {
        int r = g_rows[m];
        int sp = r >> 5, t = r & 31;
        int b = sp >> 4, mm = sp & 15;
        int src = min(max(starts[b * MS_ + mm] + t, 0), S_ - 1);
        const float* base = &hidden[((size_t)b * S_ + src) * D_ + k0];
#pragma unroll
        for (int e = 0; e < 4; e++) {
            float4 v = *reinterpret_cast<const float4*>(base + 4 * e);
            xs[4 * e + 0] = v.x; xs[4 * e + 1] = v.y;
            xs[4 * e + 2] = v.z; xs[4 * e + 3] = v.w;
        }
    } else {
#pragma unroll
        for (int e = 0; e < 16; e++) xs[e] = 0.f;
    }
    unsigned slots[8];
#pragma unroll
    for (int t = 0; t < 4; t++) {
        slots[2 * t]     = pack_h2(xs[2 * t],     xs[2 * t + 1]);
        slots[2 * t + 1] = pack_h2(xs[2 * t + 8], xs[2 * t + 9]);
    }
    unsigned* dst = &g_A16[(size_t)m * KP2 + ks * 8];
    *reinterpret_cast<uint4*>(dst)     = *reinterpret_cast<uint4*>(&slots[0]);
    *reinterpret_cast<uint4*>(dst + 4) = *reinterpret_cast<uint4*>(&slots[4]);
}

// ---------------------------------------------------------------------------
// fp16 GEMM: 4 warps, 64x64 warp tile, cp.async double-buffered. (frozen)
// ---------------------------------------------------------------------------
#define MMA_FP16(d, a, b)                                                       \
    asm volatile("mma.sync.aligned.m16n8k16.row.col.f32.f16.f16.f32 "           \
                 "{%0,%1,%2,%3}, {%4,%5,%6,%7}, {%8,%9}, {%0,%1,%2,%3};"        \
                 : "+f"(d[0]), "+f"(d[1]), "+f"(d[2]), "+f"(d[3])               \
                 : "r"(a[0]), "r"(a[1]), "r"(a[2]), "r"(a[3]),                  \
                   "r"(b[0]), "r"(b[1]));

__device__ __forceinline__ void cp16(unsigned* smem_ptr, const unsigned* gptr) {
    unsigned saddr = (unsigned)__cvta_generic_to_shared(smem_ptr);
    asm volatile("cp.async.cg.shared.global [%0], [%1], 16;" :: "r"(saddr), "l"(gptr));
}

#define MAT_TILE (128 * PITCH)          // 5120 u32
#define STG      (2 * MAT_TILE)         // 10240 u32/stage (40KB)

extern __shared__ unsigned smem_u[];

__global__ __launch_bounds__(128, 2) void gemm_tc(void) {
    const int cnt = g_cnt;
    const int m0  = blockIdx.y * 128;
    if (m0 >= cnt) return;
    const int n0  = blockIdx.x * 128;

    __shared__ int rowIdx[128];
    int tid = threadIdx.x;
    rowIdx[tid] = (m0 + tid < cnt) ? g_rows[m0 + tid] : -1;

    float acc[32][4];
#pragma unroll
    for (int i = 0; i < 32; i++)
#pragma unroll
        for (int q = 0; q < 4; q++) acc[i][q] = 0.f;

    int lane = tid & 31, wid = tid >> 5;
    int wm = wid >> 1, wn = wid & 1;
    int g = lane >> 2, tg = lane & 3;

    auto load_stage = [&](int stage, int k0u) {
        unsigned* As = smem_u + stage * STG;
        unsigned* Bs = As + MAT_TILE;
#pragma unroll
        for (int i = 0; i < 8; i++) {
            int id = tid + i * 128;
            int m = id >> 3, c = id & 7;
            cp16(&As[m * PITCH + c * 4], &g_A16[(size_t)(m0 + m) * KP2 + k0u + c * 4]);
        }
#pragma unroll
        for (int i = 0; i < 8; i++) {
            int id = tid + i * 128;
            int n = id >> 3, c = id & 7;
            cp16(&Bs[n * PITCH + c * 4], &g_B16[(size_t)(n0 + n) * KP2 + k0u + c * 4]);
        }
    };

    const int NITER = KP / KC;   // 13
    load_stage(0, 0);
    asm volatile("cp.async.commit_group;");

    for (int it = 0; it < NITER; it++) {
        if (it + 1 < NITER) load_stage((it + 1) & 1, (it + 1) * KC2);
        asm volatile("cp.async.commit_group;");
        asm volatile("cp.async.wait_group 1;");
        __syncthreads();

        const unsigned* As = smem_u + (it & 1) * STG;
        const unsigned* Bs = As + MAT_TILE;

#pragma unroll
        for (int ks = 0; ks < 4; ks++) {
            int kp = ks * 8;
            unsigned af[4][4];
#pragma unroll
            for (int mt = 0; mt < 4; mt++) {
                int r0 = wm * 64 + mt * 16 + g;
                ull v0 = *reinterpret_cast<const ull*>(As + r0 * PITCH + kp + 2 * tg);
                ull v1 = *reinterpret_cast<const ull*>(As + (r0 + 8) * PITCH + kp + 2 * tg);
                af[mt][0] = (unsigned)v0;
                af[mt][2] = (unsigned)(v0 >> 32);
                af[mt][1] = (unsigned)v1;
                af[mt][3] = (unsigned)(v1 >> 32);
            }
            unsigned bf[8][2];
#pragma unroll
            for (int nt = 0; nt < 8; nt++) {
                int c = wn * 64 + nt * 8 + g;
                ull v = *reinterpret_cast<const ull*>(Bs + c * PITCH + kp + 2 * tg);
                bf[nt][0] = (unsigned)v;
                bf[nt][1] = (unsigned)(v >> 32);
            }
#pragma unroll
            for (int mt = 0; mt < 4; mt++)
#pragma unroll
                for (int nt = 0; nt < 8; nt++)
                    MMA_FP16(acc[mt * 8 + nt], af[mt], bf[nt]);
        }
        __syncthreads();
    }

#pragma unroll
    for (int mt = 0; mt < 4; mt++) {
        int lr0 = wm * 64 + mt * 16 + g;
#pragma unroll
        for (int nt = 0; nt < 8; nt++) {
            int c = n0 + wn * 64 + nt * 8 + tg * 2;
            if (c >= NCOLS) continue;
            float* a = acc[mt * 8 + nt];
            float2 bias = *reinterpret_cast<const float2*>(&g_biasC[c]);
            int dirb = (c >= G4H);
            int cc   = c - dirb * G4H;
#pragma unroll
            for (int h = 0; h < 2; h++) {
                int lr = lr0 + h * 8;
                if (m0 + lr < cnt) {
                    int rid = rowIdx[lr];
                    unsigned hv = pack_h2(a[h * 2 + 0] + bias.x, a[h * 2 + 1] + bias.y);
                    *reinterpret_cast<unsigned*>(&g_Zh[dirb][(size_t)rid * G4H + cc]) = hv;
                }
            }
        }
    }
}

// ---------------------------------------------------------------------------
// Recurrence: 4 spans/CTA, 512 CTAs descending. Inner loop in fma.rn.f32x2
// with k-paired accumulators: weights arrive pre-paired (zero pack overhead),
// h pairs are LDS.64 broadcasts. 32 FMA2 + 4 LDG + 8 LDS per 4k (was 72 inst).
// ---------------------------------------------------------------------------
__device__ __forceinline__ float fast_sig(float x)  { return 1.f / (1.f + __expf(-x)); }
__device__ __forceinline__ float fast_tanh(float x) {
    float t = __expf(-2.f * x);
    return __fdividef(1.f - t, 1.f + t);
}

__global__ __launch_bounds__(224) void lstm_kernel(const int* __restrict__ span_lens) {
    __shared__ float h_sh[2][PSPAN][H_];    // [buf][span][k], 8B-aligned rows (H_=200 even)
    __shared__ int   sp_sh[PSPAN];
    __shared__ int   len_sh[PSPAN];

    int tid = threadIdx.x;
    int dir = blockIdx.y;
    int u   = tid;
    bool act = u < H_;
    int n0  = blockIdx.x * PSPAN;

    const __half* Zh = g_Zh[dir];
    const float4 (*Wq)[NCHK][H_] = g_Wq[dir];   // [gate][chunk][u]

    if (tid < PSPAN) {
        int sp = g_order[n0 + tid];
        sp_sh[tid]  = sp;
        len_sh[tid] = min(max(span_lens[sp], 0), T_);
    }
    {
        float* hz = (float*)h_sh;
        for (int i = tid; i < 2 * PSPAN * H_; i += 224) hz[i] = 0.f;
    }
    __syncthreads();

    int maxL = 0;
#pragma unroll
    for (int p = 0; p < PSPAN; p++) maxL = max(maxL, len_sh[p]);

    float c_st[PSPAN], feat[PSPAN], hreg[PSPAN];
#pragma unroll
    for (int p = 0; p < PSPAN; p++) { c_st[p] = 0.f; feat[p] = 0.f; hreg[p] = 0.f; }

    int buf = 0;
    for (int s = 0; s < maxL; s++) {
        if (act) {
            float z0[PSPAN], z1[PSPAN], z2[PSPAN], z3[PSPAN];
#pragma unroll
            for (int p = 0; p < PSPAN; p++) {
                int L = len_sh[p];
                int t = dir ? (L - 1 - s) : s;
                if (s >= L) t = 0;
                const __half* zr = Zh + ((size_t)sp_sh[p] * T_ + t) * G4H;
                z0[p] = __half2float(zr[u]);
                z1[p] = __half2float(zr[H_ + u]);
                z2[p] = __half2float(zr[2 * H_ + u]);
                z3[p] = __half2float(zr[3 * H_ + u]);
            }

            // k-paired accumulators: acc[gate][span] holds (even-k, odd-k) sums
            ull acc[4][PSPAN];
#pragma unroll
            for (int gq = 0; gq < 4; gq++)
#pragma unroll
                for (int p = 0; p < PSPAN; p++) acc[gq][p] = 0ull;

#pragma unroll 2
            for (int cch = 0; cch < NCHK; cch++) {
                float4 wq0 = Wq[0][cch][u];
                float4 wq1 = Wq[1][cch][u];
                float4 wq2 = Wq[2][cch][u];
                float4 wq3 = Wq[3][cch][u];
                ull w0a = reinterpret_cast<ull*>(&wq0)[0], w0b = reinterpret_cast<ull*>(&wq0)[1];
                ull w1a = reinterpret_cast<ull*>(&wq1)[0], w1b = reinterpret_cast<ull*>(&wq1)[1];
                ull w2a = reinterpret_cast<ull*>(&wq2)[0], w2b = reinterpret_cast<ull*>(&wq2)[1];
                ull w3a = reinterpret_cast<ull*>(&wq3)[0], w3b = reinterpret_cast<ull*>(&wq3)[1];
#pragma unroll
                for (int p = 0; p < PSPAN; p++) {
                    const ull* hp = reinterpret_cast<const ull*>(&h_sh[buf][p][4 * cch]);
                    ull h0 = hp[0];   // (h_k, h_k+1) broadcast
                    ull h1 = hp[1];   // (h_k+2, h_k+3)
                    FMA_X2(acc[0][p], w0a, h0);
                    FMA_X2(acc[0][p], w0b, h1);
                    FMA_X2(acc[1][p], w1a, h0);
                    FMA_X2(acc[1][p], w1b, h1);
                    FMA_X2(acc[2][p], w2a, h0);
                    FMA_X2(acc[2][p], w2b, h1);
                    FMA_X2(acc[3][p], w3a, h0);
                    FMA_X2(acc[3][p], w3b, h1);
                }
            }

#pragma unroll
            for (int p = 0; p < PSPAN; p++) {
                float2 v0 = *reinterpret_cast<float2*>(&acc[0][p]);
                float2 v1 = *reinterpret_cast<float2*>(&acc[1][p]);
                float2 v2 = *reinterpret_cast<float2*>(&acc[2][p]);
                float2 v3 = *reinterpret_cast<float2*>(&acc[3][p]);
                float a0 = z0[p] + v0.x + v0.y;
                float a1 = z1[p] + v1.x + v1.y;
                float a2 = z2[p] + v2.x + v2.y;
                float a3 = z3[p] + v3.x + v3.y;
                if (s < len_sh[p]) {
                    float ig = fast_sig(a0);
                    float fg = fast_sig(a1);
                    float gg = fast_tanh(a2);
                    float og = fast_sig(a3);
                    float cn = fg * c_st[p] + ig * gg;
                    c_st[p] = cn;
                    hreg[p] = og * fast_tanh(cn);
                    feat[p] += hreg[p];
                }
                h_sh[buf ^ 1][p][u] = hreg[p];
            }
        }
        __syncthreads();
        buf ^= 1;
    }

    if (act) {
#pragma unroll
        for (int p = 0; p < PSPAN; p++)
            g_feats[(size_t)sp_sh[p] * (2 * H_) + dir * H_ + u] = feat[p];
    }
}

// ---------------------------------------------------------------------------
// logits
// ---------------------------------------------------------------------------
__global__ __launch_bounds__(192) void logits_kernel(const float* __restrict__ slot_embs,
                                                     const float* __restrict__ slot_mask,
                                                     float* __restrict__ out) {
    __shared__ float f_sm[16][2 * H_];
    __shared__ float se_sm[2 * H_ * NS_];

    int tid = threadIdx.x;
    int n0  = blockIdx.x * 16;

    for (int i = tid; i < 2 * H_ * NS_; i += blockDim.x) se_sm[i] = slot_embs[i];
    for (int i = tid; i < 16 * 2 * H_; i += blockDim.x) {
        int sp = i / (2 * H_), h = i % (2 * H_);
        f_sm[sp][h] = g_feats[(size_t)(n0 + sp) * (2 * H_) + h];
    }
    __syncthreads();

    int sp = tid / NS_, ns = tid % NS_;
    float acc = 0.f;
#pragma unroll 8
    for (int h = 0; h < 2 * H_; h++) acc += f_sm[sp][h] * se_sm[h * NS_ + ns];
    out[(n0 + sp) * NS_ + ns] = acc * slot_mask[n0 + sp];
}

// ---------------------------------------------------------------------------
extern "C" void kernel_launch(void* const* d_in, const int* in_sizes, int n_in,
                              void* d_out, int out_size) {
    const float* hidden    = (const float*)d_in[0];
    const float* Wih_f     = (const float*)d_in[1];
    const float* Whh_f     = (const float*)d_in[2];
    const float* bih_f     = (const float*)d_in[3];
    const float* bhh_f     = (const float*)d_in[4];
    const float* Wih_b     = (const float*)d_in[5];
    const float* Whh_b     = (const float*)d_in[6];
    const float* bih_b     = (const float*)d_in[7];
    const float* bhh_b     = (const float*)d_in[8];
    const float* slot_embs = (const float*)d_in[9];
    const int*   starts    = (const int*)d_in[10];
    const int*   lens      = (const int*)d_in[11];
    const float* slot_mask = (const float*)d_in[12];
    float* out = (float*)d_out;

    const int gemm_smem = 2 * STG * (int)sizeof(unsigned);   // 81920 B
    cudaFuncSetAttribute(gemm_tc, cudaFuncAttributeMaxDynamicSharedMemorySize, gemm_smem);

    // lstm stays the 4th launch -> lands in ncu's profile window
    packprep_kernel<<<256, 1024>>>(Wih_f, Whh_f, bih_f, bhh_f,
                                   Wih_b, Whh_b, bih_b, bhh_b, lens);

    gather_split<<<(MROWS * NSLICE + 255) / 256, 256>>>(hidden, starts);

    dim3 ggrid(NCPAD / 128, MROWS / 128);
    gemm_tc<<<ggrid, 128, gemm_smem>>>();

    dim3 lgrid(NSPAN / PSPAN, 2);   // 512 CTAs, 4 descending-length spans each
    lstm_kernel<<<lgrid, 224>>>(lens);

    logits_kernel<<<NSPAN / 16, 192>>>(slot_embs, slot_mask, out);
}